// round 1
// baseline (speedup 1.0000x reference)
#include <cuda_runtime.h>

#define B_ 64
#define G_ 512
#define H_ 512
#define P_ 64
#define S_ 256
#define TWO_PI_F 6.283185307179586f

// Scratch for the tiny MLP results (allocation-free rule: __device__ globals).
__device__ float g_K1[B_ * P_];
__device__ float g_K2[B_ * P_];

// ---------------------------------------------------------------------------
// Kernel 1: K1[b,p], K2[b,p] = heads of relu(Z_g @ W_l + b_l).
// Double accumulation: our K error must stay below the reference's own fp32
// rounding, since the sin argument scales it by up to l=255.
// One block per b, 512 threads (one per hidden unit h).
// ---------------------------------------------------------------------------
__global__ void mlp_kernel(const float* __restrict__ Zg,
                           const float* __restrict__ Wl,
                           const float* __restrict__ bl,
                           const float* __restrict__ W1,
                           const float* __restrict__ b1,
                           const float* __restrict__ W2,
                           const float* __restrict__ b2) {
    const int b = blockIdx.x;
    const int t = threadIdx.x;  // 0..511

    __shared__ float zg[G_];
    __shared__ float x[H_];

    zg[t] = Zg[b * G_ + t];
    __syncthreads();

    // x[t] = relu(dot(zg, W_l[:, t]) + bl[t]); W_l reads coalesced across t.
    double acc = (double)bl[t];
#pragma unroll 8
    for (int g = 0; g < G_; ++g)
        acc += (double)zg[g] * (double)Wl[g * H_ + t];
    float xv = (float)acc;
    x[t] = xv > 0.0f ? xv : 0.0f;
    __syncthreads();

    // Threads 0..63 -> K1, threads 64..127 -> K2. Coalesced W1/W2 row reads.
    if (t < 2 * P_) {
        const int p = t & (P_ - 1);
        const float* __restrict__ W  = (t < P_) ? W1 : W2;
        const float* __restrict__ bb = (t < P_) ? b1 : b2;
        double a = (double)bb[p];
#pragma unroll 8
        for (int h = 0; h < H_; ++h)
            a += (double)x[h] * (double)W[h * P_ + p];
        if (t < P_) g_K1[b * P_ + p] = (float)a;
        else        g_K2[b * P_ + p] = (float)a;
    }
}

// ---------------------------------------------------------------------------
// Kernel 2: out[b,p,l,m] = sin(K1*l + K2*m + phi*2pi)
//                        = sin(K1*l)*cos(K2*m+ph) + cos(K1*l)*sin(K2*m+ph)
// One block per (b,p): 512 sincosf to build tables, then 65536 outputs at
// 2 FFMA each. 256 threads; thread t owns float4 column (t&63) and row
// residue (t>>6); 64 iterations cover all 256 rows. Streaming stores.
// ---------------------------------------------------------------------------
__global__ void __launch_bounds__(S_) fill_kernel(const float* __restrict__ phi,
                                                  float* __restrict__ out) {
    const int bp = blockIdx.x;       // b*P + p
    const int t  = threadIdx.x;      // 0..255

    __shared__ float sA[S_], cA[S_], sB[S_], cB[S_];

    const float K1 = g_K1[bp];
    const float K2 = g_K2[bp];
    const float ph = phi[bp] * TWO_PI_F;

    {
        float s, c;
        sincosf(K1 * (float)t, &s, &c);
        sA[t] = s; cA[t] = c;
        sincosf(K2 * (float)t + ph, &s, &c);
        sB[t] = s; cB[t] = c;
    }
    __syncthreads();

    const int   mi = t & 63;   // float4 index within a row (m dimension)
    const int   r0 = t >> 6;   // row residue 0..3
    const float4 sb = reinterpret_cast<const float4*>(sB)[mi];
    const float4 cb = reinterpret_cast<const float4*>(cB)[mi];

    float4* __restrict__ out4 =
        reinterpret_cast<float4*>(out + (size_t)bp * (S_ * S_));

#pragma unroll 8
    for (int i = 0; i < S_ / 4; ++i) {
        const int l  = (i << 2) + r0;
        const float sa = sA[l];
        const float ca = cA[l];
        float4 r;
        r.x = sa * cb.x + ca * sb.x;
        r.y = sa * cb.y + ca * sb.y;
        r.z = sa * cb.z + ca * sb.z;
        r.w = sa * cb.w + ca * sb.w;
        __stcs(&out4[l * (S_ / 4) + mi], r);  // streaming: bypass L2 persistence
    }
}

extern "C" void kernel_launch(void* const* d_in, const int* in_sizes, int n_in,
                              void* d_out, int out_size) {
    const float* Zg  = (const float*)d_in[0];
    const float* phi = (const float*)d_in[1];
    const float* Wl  = (const float*)d_in[2];
    const float* bl  = (const float*)d_in[3];
    const float* W1  = (const float*)d_in[4];
    const float* b1  = (const float*)d_in[5];
    const float* W2  = (const float*)d_in[6];
    const float* b2  = (const float*)d_in[7];
    float* out = (float*)d_out;

    mlp_kernel<<<B_, H_>>>(Zg, Wl, bl, W1, b1, W2, b2);
    fill_kernel<<<B_ * P_, S_>>>(phi, out);
}

// round 4
// speedup vs baseline: 2.0371x; 2.0371x over previous
#include <cuda_runtime.h>

#define B_ 64
#define G_ 512
#define H_ 512
#define P_ 64
#define S_ 256
#define TWO_PI_F 6.283185307179586f

// Scratch for the tiny MLP results (allocation-free rule: __device__ globals).
__device__ float g_K1[B_ * P_];
__device__ float g_K2[B_ * P_];

// Kahan compensated add. _rn intrinsics block FFMA contraction / reassociation
// so the correction term survives ptxas.
__device__ __forceinline__ void kahan_add(float term, float& s, float& c) {
    float y = __fsub_rn(term, c);
    float t = __fadd_rn(s, y);
    c = __fsub_rn(__fsub_rn(t, s), y);
    s = t;
}

// ---------------------------------------------------------------------------
// Kernel 1: K1[b,p], K2[b,p] = heads of relu(Z_g @ W_l + b_l).
// fp32 Kahan accumulation (4 independent accumulators for ILP) — near-exact
// dot products at FFMA-pipe speed instead of the FP64 crawl.
// One block per b, 512 threads.
// ---------------------------------------------------------------------------
__global__ void __launch_bounds__(H_) mlp_kernel(const float* __restrict__ Zg,
                           const float* __restrict__ Wl,
                           const float* __restrict__ bl,
                           const float* __restrict__ W1,
                           const float* __restrict__ b1,
                           const float* __restrict__ W2,
                           const float* __restrict__ b2) {
    const int b = blockIdx.x;
    const int t = threadIdx.x;  // 0..511

    __shared__ float zg[G_];
    __shared__ float x[H_];

    zg[t] = Zg[b * G_ + t];
    __syncthreads();

    // x[t] = relu(dot(zg, W_l[:, t]) + bl[t]); W_l reads coalesced across t.
    {
        float s0 = 0.f, s1 = 0.f, s2 = 0.f, s3 = 0.f;
        float c0 = 0.f, c1 = 0.f, c2 = 0.f, c3 = 0.f;
#pragma unroll 4
        for (int g = 0; g < G_; g += 4) {
            kahan_add(__fmul_rn(zg[g + 0], Wl[(g + 0) * H_ + t]), s0, c0);
            kahan_add(__fmul_rn(zg[g + 1], Wl[(g + 1) * H_ + t]), s1, c1);
            kahan_add(__fmul_rn(zg[g + 2], Wl[(g + 2) * H_ + t]), s2, c2);
            kahan_add(__fmul_rn(zg[g + 3], Wl[(g + 3) * H_ + t]), s3, c3);
        }
        // Combine: partials are each ~exact; residual compensations added back.
        float s = __fadd_rn(__fadd_rn(s0, s1), __fadd_rn(s2, s3));
        float c = __fadd_rn(__fadd_rn(c0, c1), __fadd_rn(c2, c3));
        float xv = __fadd_rn(__fsub_rn(s, c), bl[t]);
        x[t] = xv > 0.0f ? xv : 0.0f;
    }
    __syncthreads();

    // Threads 0..63 -> K1, threads 64..127 -> K2. Coalesced W1/W2 row reads.
    if (t < 2 * P_) {
        const int p = t & (P_ - 1);
        const float* __restrict__ W  = (t < P_) ? W1 : W2;
        const float* __restrict__ bb = (t < P_) ? b1 : b2;
        float s0 = 0.f, s1 = 0.f, s2 = 0.f, s3 = 0.f;
        float c0 = 0.f, c1 = 0.f, c2 = 0.f, c3 = 0.f;
#pragma unroll 4
        for (int h = 0; h < H_; h += 4) {
            kahan_add(__fmul_rn(x[h + 0], W[(h + 0) * P_ + p]), s0, c0);
            kahan_add(__fmul_rn(x[h + 1], W[(h + 1) * P_ + p]), s1, c1);
            kahan_add(__fmul_rn(x[h + 2], W[(h + 2) * P_ + p]), s2, c2);
            kahan_add(__fmul_rn(x[h + 3], W[(h + 3) * P_ + p]), s3, c3);
        }
        float s = __fadd_rn(__fadd_rn(s0, s1), __fadd_rn(s2, s3));
        float c = __fadd_rn(__fadd_rn(c0, c1), __fadd_rn(c2, c3));
        float k = __fadd_rn(__fsub_rn(s, c), bb[p]);
        if (t < P_) g_K1[b * P_ + p] = k;
        else        g_K2[b * P_ + p] = k;
    }
}

// ---------------------------------------------------------------------------
// Kernel 2: out[b,p,l,m] = sin(K1*l + K2*m + phi*2pi)
//                        = sin(K1*l)*cos(K2*m+ph) + cos(K1*l)*sin(K2*m+ph)
// One block per (b,p): 512 sincosf to build tables, then 65536 outputs at
// 2 FFMA each. Streaming 128-bit stores; measured 85.6% DRAM SOL in R1.
// ---------------------------------------------------------------------------
__global__ void __launch_bounds__(S_) fill_kernel(const float* __restrict__ phi,
                                                  float* __restrict__ out) {
    const int bp = blockIdx.x;       // b*P + p
    const int t  = threadIdx.x;      // 0..255

    __shared__ float sA[S_], cA[S_], sB[S_], cB[S_];

    const float K1 = g_K1[bp];
    const float K2 = g_K2[bp];
    const float ph = phi[bp] * TWO_PI_F;

    {
        float s, c;
        sincosf(K1 * (float)t, &s, &c);
        sA[t] = s; cA[t] = c;
        sincosf(K2 * (float)t + ph, &s, &c);
        sB[t] = s; cB[t] = c;
    }
    __syncthreads();

    const int   mi = t & 63;   // float4 index within a row (m dimension)
    const int   r0 = t >> 6;   // row residue 0..3
    const float4 sb = reinterpret_cast<const float4*>(sB)[mi];
    const float4 cb = reinterpret_cast<const float4*>(cB)[mi];

    float4* __restrict__ out4 =
        reinterpret_cast<float4*>(out + (size_t)bp * (S_ * S_));

#pragma unroll 8
    for (int i = 0; i < S_ / 4; ++i) {
        const int l  = (i << 2) + r0;
        const float sa = sA[l];
        const float ca = cA[l];
        float4 r;
        r.x = sa * cb.x + ca * sb.x;
        r.y = sa * cb.y + ca * sb.y;
        r.z = sa * cb.z + ca * sb.z;
        r.w = sa * cb.w + ca * sb.w;
        __stcs(&out4[l * (S_ / 4) + mi], r);  // streaming store
    }
}

extern "C" void kernel_launch(void* const* d_in, const int* in_sizes, int n_in,
                              void* d_out, int out_size) {
    const float* Zg  = (const float*)d_in[0];
    const float* phi = (const float*)d_in[1];
    const float* Wl  = (const float*)d_in[2];
    const float* bl  = (const float*)d_in[3];
    const float* W1  = (const float*)d_in[4];
    const float* b1  = (const float*)d_in[5];
    const float* W2  = (const float*)d_in[6];
    const float* b2  = (const float*)d_in[7];
    float* out = (float*)d_out;

    mlp_kernel<<<B_, H_>>>(Zg, Wl, bl, W1, b1, W2, b2);
    fill_kernel<<<B_ * P_, S_>>>(phi, out);
}

// round 6
// speedup vs baseline: 2.3222x; 1.1400x over previous
#include <cuda_runtime.h>

#define B_ 64
#define G_ 512
#define H_ 512
#define P_ 64
#define S_ 256
#define TWO_PI_F 6.283185307179586f

// Scratch for the tiny MLP results (allocation-free rule: __device__ globals).
__device__ float g_K1[B_ * P_];
__device__ float g_K2[B_ * P_];

// Kahan compensated add (stage-2 only; cheap there, keeps K near-exact).
__device__ __forceinline__ void kahan_add(float term, float& s, float& c) {
    float y = __fsub_rn(term, c);
    float t = __fadd_rn(s, y);
    c = __fsub_rn(__fsub_rn(t, s), y);
    s = t;
}

// ---------------------------------------------------------------------------
// Kernel 1: K1[b,p], K2[b,p] = heads of relu(Z_g @ W_l + b_l).
// Stage 1: float4 weight loads, plain FFMA, G split 4 ways across threads
//          (thread t: g-chunk = t>>7, column group = t&127 -> cols 4c..4c+3).
// Stage 2: all 512 threads, H split 4 ways, Kahan partials, smem reduce.
// One block per b, 512 threads.
// ---------------------------------------------------------------------------
__global__ void __launch_bounds__(H_) mlp_kernel(const float* __restrict__ Zg,
                           const float* __restrict__ Wl,
                           const float* __restrict__ bl,
                           const float* __restrict__ W1,
                           const float* __restrict__ b1,
                           const float* __restrict__ W2,
                           const float* __restrict__ b2) {
    const int b = blockIdx.x;
    const int t = threadIdx.x;  // 0..511

    __shared__ float  zg[G_];
    __shared__ float4 ps[4][H_ / 4];   // stage-1 partials [g-chunk][col-group]
    __shared__ float  x[H_];
    __shared__ float  red[4][2 * P_];  // stage-2 partials [h-chunk][half*64+p]

    zg[t] = Zg[b * G_ + t];
    __syncthreads();

    // ---- Stage 1: x = relu(zg @ Wl + bl) ----
    {
        const int col4 = t & 127;      // column group: cols 4*col4 .. 4*col4+3
        const int gc   = t >> 7;       // g-chunk 0..3
        const float4* __restrict__ W4 = reinterpret_cast<const float4*>(Wl);
        float4 a = make_float4(0.f, 0.f, 0.f, 0.f);
        const int g0 = gc * 128;
#pragma unroll 8
        for (int g = g0; g < g0 + 128; ++g) {
            const float  z = zg[g];
            const float4 w = W4[g * (H_ / 4) + col4];  // LDG.128, coalesced
            a.x = fmaf(z, w.x, a.x);
            a.y = fmaf(z, w.y, a.y);
            a.z = fmaf(z, w.z, a.z);
            a.w = fmaf(z, w.w, a.w);
        }
        ps[gc][col4] = a;
    }
    __syncthreads();

    if (t < H_ / 4) {
        float4 a0 = ps[0][t], a1 = ps[1][t], a2 = ps[2][t], a3 = ps[3][t];
        const float4 bb = reinterpret_cast<const float4*>(bl)[t];
        float4 r;
        r.x = (a0.x + a1.x) + (a2.x + a3.x) + bb.x;
        r.y = (a0.y + a1.y) + (a2.y + a3.y) + bb.y;
        r.z = (a0.z + a1.z) + (a2.z + a3.z) + bb.z;
        r.w = (a0.w + a1.w) + (a2.w + a3.w) + bb.w;
        r.x = r.x > 0.f ? r.x : 0.f;
        r.y = r.y > 0.f ? r.y : 0.f;
        r.z = r.z > 0.f ? r.z : 0.f;
        r.w = r.w > 0.f ? r.w : 0.f;
        reinterpret_cast<float4*>(x)[t] = r;
    }
    __syncthreads();

    // ---- Stage 2: K1/K2 heads, Kahan, 4-way h split ----
    {
        const int p    = t & 63;
        const int half = (t >> 6) & 1;   // 0 -> K1, 1 -> K2
        const int hc   = t >> 7;         // h-chunk 0..3
        const float* __restrict__ W = half ? W2 : W1;
        float s = 0.f, c = 0.f;
        const int h0 = hc * 128;
#pragma unroll 4
        for (int h = h0; h < h0 + 128; ++h)
            kahan_add(__fmul_rn(x[h], W[h * P_ + p]), s, c);
        red[hc][t & 127] = __fsub_rn(s, c);
    }
    __syncthreads();

    if (t < 2 * P_) {
        const int p = t & 63;
        float k = (red[0][t] + red[1][t]) + (red[2][t] + red[3][t]);
        if (t < P_) { k += b1[p]; g_K1[b * P_ + p] = k; }
        else        { k += b2[p]; g_K2[b * P_ + p] = k; }
    }
}

// ---------------------------------------------------------------------------
// Kernel 2: out[b,p,l,m] = sin(K1*l + K2*m + phi*2pi)
//                        = sin(K1*l)*cos(K2*m+ph) + cos(K1*l)*sin(K2*m+ph)
// One block per (b,p): 512 sincosf to build tables, then 65536 outputs at
// 2 FFMA each. Streaming 128-bit stores; measured 86% DRAM SOL — frozen.
// ---------------------------------------------------------------------------
__global__ void __launch_bounds__(S_) fill_kernel(const float* __restrict__ phi,
                                                  float* __restrict__ out) {
    const int bp = blockIdx.x;       // b*P + p
    const int t  = threadIdx.x;      // 0..255

    __shared__ float sA[S_], cA[S_], sB[S_], cB[S_];

    const float K1 = g_K1[bp];
    const float K2 = g_K2[bp];
    const float ph = phi[bp] * TWO_PI_F;

    {
        float s, c;
        sincosf(K1 * (float)t, &s, &c);
        sA[t] = s; cA[t] = c;
        sincosf(K2 * (float)t + ph, &s, &c);
        sB[t] = s; cB[t] = c;
    }
    __syncthreads();

    const int   mi = t & 63;   // float4 index within a row (m dimension)
    const int   r0 = t >> 6;   // row residue 0..3
    const float4 sb = reinterpret_cast<const float4*>(sB)[mi];
    const float4 cb = reinterpret_cast<const float4*>(cB)[mi];

    float4* __restrict__ out4 =
        reinterpret_cast<float4*>(out + (size_t)bp * (S_ * S_));

#pragma unroll 8
    for (int i = 0; i < S_ / 4; ++i) {
        const int l  = (i << 2) + r0;
        const float sa = sA[l];
        const float ca = cA[l];
        float4 r;
        r.x = sa * cb.x + ca * sb.x;
        r.y = sa * cb.y + ca * sb.y;
        r.z = sa * cb.z + ca * sb.z;
        r.w = sa * cb.w + ca * sb.w;
        __stcs(&out4[l * (S_ / 4) + mi], r);  // streaming store
    }
}

extern "C" void kernel_launch(void* const* d_in, const int* in_sizes, int n_in,
                              void* d_out, int out_size) {
    const float* Zg  = (const float*)d_in[0];
    const float* phi = (const float*)d_in[1];
    const float* Wl  = (const float*)d_in[2];
    const float* bl  = (const float*)d_in[3];
    const float* W1  = (const float*)d_in[4];
    const float* b1  = (const float*)d_in[5];
    const float* W2  = (const float*)d_in[6];
    const float* b2  = (const float*)d_in[7];
    float* out = (float*)d_out;

    mlp_kernel<<<B_, H_>>>(Zg, Wl, bl, W1, b1, W2, b2);
    fill_kernel<<<B_ * P_, S_>>>(phi, out);
}